// round 16
// baseline (speedup 1.0000x reference)
#include <cuda_runtime.h>
#include <cuda_bf16.h>
#include <cstdint>

// time_embeddings: out[b, i] = sin/cos(time[b] * 10000^(-(i//2)/640))
// B = 65536, DIM = 1280, fp32 out. HBM-write-bound: 335.5 MB written,
// best 51.2us (~6.55 TB/s effective, ~86% of spec).
//
// Round-16: final A/B — store eviction policy. Everything identical to the
// round-15 config (BLOCK=256/GRID=10240, 64 warps/SM, fixed-chunk mapping,
// Cody-Waite + __sincosf, 256-bit stores) except the stores drop the .cs
// evict-first hint: default write-back lets L2 accumulate full dirty lines
// and gives the DRAM controller freedom to batch writebacks. Output >> L2
// so total DRAM bytes are identical; only writeback scheduling differs.
// Measured-converged otherwise: grain, geometry, store width, TMA path,
// prefetch/MLP, occupancy all swept.

#define DIM      1280
#define C8S      (DIM / 8)     // 160 float8 chunks per row
#define BLOCK    256
#define GRID     10240         // 10240*256 threads = 160*16384 chunk slots
#define ROWSTEP  16384         // rows advanced per iteration

__global__ __launch_bounds__(BLOCK, 8)
void time_emb_kernel(const float* __restrict__ time, float* __restrict__ out, int B)
{
    const int g    = blockIdx.x * BLOCK + threadIdx.x;  // flat chunk-slot id
    const int c8   = g % C8S;                           // fixed chunk 0..159
    const int row0 = g / C8S;                           // base row 0..16383

    // rate(p) = 10000^(-p/640) = exp2(-log2(10000)/640 * p), p = i//2
    const float C = -13.287712379549449f / 640.0f;
    const int pb = 4 * c8;                  // first pair index of this chunk
    const float r0 = exp2f(C * (float)(pb + 0));
    const float r1 = exp2f(C * (float)(pb + 1));
    const float r2 = exp2f(C * (float)(pb + 2));
    const float r3 = exp2f(C * (float)(pb + 3));

    // Cody-Waite: 2*pi = HI + LO, HI=6.28125 exact for k<=160 (angle<=1000)
    const float INV2PI = 0.15915494309189535f;
    const float HI     = 6.28125f;
    const float LO     = 1.9353071795864769e-3f;

    for (int row = row0; row < B; row += ROWSTEP) {
        const float t = __ldg(&time[row]);   // warp-uniform (warp is row-pure)

        float a0 = t * r0, a1 = t * r1, a2 = t * r2, a3 = t * r3;

        float k0 = rintf(a0 * INV2PI), k1 = rintf(a1 * INV2PI);
        float k2 = rintf(a2 * INV2PI), k3 = rintf(a3 * INV2PI);

        float x0 = fmaf(k0, -LO, fmaf(k0, -HI, a0));
        float x1 = fmaf(k1, -LO, fmaf(k1, -HI, a1));
        float x2 = fmaf(k2, -LO, fmaf(k2, -HI, a2));
        float x3 = fmaf(k3, -LO, fmaf(k3, -HI, a3));

        float s0, c0, s1, c1, s2, c2, s3, c3;
        __sincosf(x0, &s0, &c0);
        __sincosf(x1, &s1, &c1);
        __sincosf(x2, &s2, &c2);
        __sincosf(x3, &s3, &c3);

        // even col -> sin, odd col -> cos; cols 8*c8 .. 8*c8+7 of this row
        float* p = out + (size_t)row * DIM + 8 * c8;
        asm volatile(
            "st.global.v8.f32 [%0], {%1, %2, %3, %4, %5, %6, %7, %8};"
            :: "l"(p),
               "f"(s0), "f"(c0), "f"(s1), "f"(c1),
               "f"(s2), "f"(c2), "f"(s3), "f"(c3)
            : "memory");
    }
}

extern "C" void kernel_launch(void* const* d_in, const int* in_sizes, int n_in,
                              void* d_out, int out_size)
{
    const float* time = (const float*)d_in[0];
    float* out = (float*)d_out;
    const int B = in_sizes[0];

    time_emb_kernel<<<GRID, BLOCK>>>(time, out, B);
}

// round 17
// speedup vs baseline: 1.0044x; 1.0044x over previous
#include <cuda_runtime.h>
#include <cuda_bf16.h>
#include <cstdint>

// time_embeddings: out[b, i] = sin/cos(time[b] * 10000^(-(i//2)/640))
// B = 65536, DIM = 1280, fp32 out. HBM-write-bound: 335.5 MB written.
//
// FINAL — converged at 51.2us = ~6.55 TB/s effective write bandwidth
// (~86% of 8 TB/s spec), rel_err 7.16e-6. Complete A/B ledger:
//   grain sweep (888/3552/7104/8192/16384): convex, min here
//   256-bit vs 128-bit stores: 256-bit kept
//   TMA bulk-store path: slower (+2.9us) — rejected
//   one-wave persistent: slower (skew-serialized) — rejected
//   load prefetch / MLP batching: neutral — rejected
//   occupancy 60 vs 64 warps/SM: equal; 64 kept
//   .cs vs default eviction: .cs equal-or-better; kept
//
// Design:
//  - thread <-> fixed float8 chunk (c8 = g % 160); every warp row-pure
//    (160 % 32 == 0) -> warp-uniform time[] load, perfectly coalesced
//    5120 B row segments.
//  - GRID=10240 x BLOCK=256: 8 blocks/SM = 64 warps/SM; grid stride
//    10240*256 = 160*16384 so chunk is iteration-invariant and every
//    thread runs exactly 4 uniform iterations (B=65536).
//  - rates exp2f'd once per thread, reused across all 4 rows.
//  - Cody-Waite reduction (2pi = 6.28125 + LO; k<=160 exact for t<1000)
//    then __sincosf on |x|<=pi: MUFU-cheap, rel_err 7.2e-6.
//  - st.global.cs.v8.f32: 256-bit streaming stores.
//  - 32 regs, no smem, no barriers, no divergence.

#define DIM      1280
#define C8S      (DIM / 8)     // 160 float8 chunks per row
#define BLOCK    256
#define GRID     10240         // 10240*256 threads = 160*16384 chunk slots
#define ROWSTEP  16384         // rows advanced per iteration

__global__ __launch_bounds__(BLOCK, 8)
void time_emb_kernel(const float* __restrict__ time, float* __restrict__ out, int B)
{
    const int g    = blockIdx.x * BLOCK + threadIdx.x;  // flat chunk-slot id
    const int c8   = g % C8S;                           // fixed chunk 0..159
    const int row0 = g / C8S;                           // base row 0..16383

    // rate(p) = 10000^(-p/640) = exp2(-log2(10000)/640 * p), p = i//2
    const float C = -13.287712379549449f / 640.0f;
    const int pb = 4 * c8;                  // first pair index of this chunk
    const float r0 = exp2f(C * (float)(pb + 0));
    const float r1 = exp2f(C * (float)(pb + 1));
    const float r2 = exp2f(C * (float)(pb + 2));
    const float r3 = exp2f(C * (float)(pb + 3));

    // Cody-Waite: 2*pi = HI + LO, HI=6.28125 exact for k<=160 (angle<=1000)
    const float INV2PI = 0.15915494309189535f;
    const float HI     = 6.28125f;
    const float LO     = 1.9353071795864769e-3f;

    for (int row = row0; row < B; row += ROWSTEP) {
        const float t = __ldg(&time[row]);   // warp-uniform (warp is row-pure)

        float a0 = t * r0, a1 = t * r1, a2 = t * r2, a3 = t * r3;

        float k0 = rintf(a0 * INV2PI), k1 = rintf(a1 * INV2PI);
        float k2 = rintf(a2 * INV2PI), k3 = rintf(a3 * INV2PI);

        float x0 = fmaf(k0, -LO, fmaf(k0, -HI, a0));
        float x1 = fmaf(k1, -LO, fmaf(k1, -HI, a1));
        float x2 = fmaf(k2, -LO, fmaf(k2, -HI, a2));
        float x3 = fmaf(k3, -LO, fmaf(k3, -HI, a3));

        float s0, c0, s1, c1, s2, c2, s3, c3;
        __sincosf(x0, &s0, &c0);
        __sincosf(x1, &s1, &c1);
        __sincosf(x2, &s2, &c2);
        __sincosf(x3, &s3, &c3);

        // even col -> sin, odd col -> cos; cols 8*c8 .. 8*c8+7 of this row
        float* p = out + (size_t)row * DIM + 8 * c8;
        asm volatile(
            "st.global.cs.v8.f32 [%0], {%1, %2, %3, %4, %5, %6, %7, %8};"
            :: "l"(p),
               "f"(s0), "f"(c0), "f"(s1), "f"(c1),
               "f"(s2), "f"(c2), "f"(s3), "f"(c3)
            : "memory");
    }
}

extern "C" void kernel_launch(void* const* d_in, const int* in_sizes, int n_in,
                              void* d_out, int out_size)
{
    const float* time = (const float*)d_in[0];
    float* out = (float*)d_out;
    const int B = in_sizes[0];

    time_emb_kernel<<<GRID, BLOCK>>>(time, out, B);
}